// round 1
// baseline (speedup 1.0000x reference)
#include <cuda_runtime.h>
#include <cstddef>

#define D_MODEL   1024
#define NUM_HEADS 16
#define DEPTH     64
#define BATCH     2
#define SEQ       2048
#define M_ROWS    (BATCH * SEQ)   // 4096

// ---------------------------------------------------------------------------
// Scratch (static device globals; no allocations anywhere)
// ---------------------------------------------------------------------------
__device__ float g_qh[BATCH * NUM_HEADS * SEQ * DEPTH];   // [B,H,S,64]
__device__ float g_kh[BATCH * NUM_HEADS * SEQ * DEPTH];
__device__ float g_vh[BATCH * NUM_HEADS * SEQ * DEPTH];
__device__ float g_att[BATCH * SEQ * D_MODEL];            // [B,S,H*64] (concat layout)

// ---------------------------------------------------------------------------
// GEMM: C = A(M,K) @ W^T(N,K) + bias,  M=4096, N=K=1024
// head_split=1: scatter output to [B,H,S,64]; else row-major [M,N]
// 128x128 block, BK=8, 256 threads, 8x8 per thread
// ---------------------------------------------------------------------------
#define GBM 128
#define GBN 128
#define GBK 8

__global__ __launch_bounds__(256) void gemm_bias_kernel(
    const float* __restrict__ A, const float* __restrict__ W,
    const float* __restrict__ bias, float* __restrict__ C, int head_split)
{
    __shared__ float As[GBK][GBM];
    __shared__ float Ws[GBK][GBN];

    const int tid = threadIdx.x;
    const int m0 = blockIdx.y * GBM;
    const int n0 = blockIdx.x * GBN;
    const int tx = tid & 15;       // 0..15 -> n
    const int ty = tid >> 4;       // 0..15 -> m

    float acc[8][8];
#pragma unroll
    for (int i = 0; i < 8; i++)
#pragma unroll
        for (int j = 0; j < 8; j++) acc[i][j] = 0.f;

    const int loadRow = tid >> 1;        // 0..127
    const int loadCol = (tid & 1) * 4;   // 0 or 4
    const float* Aptr = A + (size_t)(m0 + loadRow) * D_MODEL + loadCol;
    const float* Wptr = W + (size_t)(n0 + loadRow) * D_MODEL + loadCol;

    for (int k0 = 0; k0 < D_MODEL; k0 += GBK) {
        float4 av = *(const float4*)(Aptr + k0);
        float4 wv = *(const float4*)(Wptr + k0);
        As[loadCol + 0][loadRow] = av.x;
        As[loadCol + 1][loadRow] = av.y;
        As[loadCol + 2][loadRow] = av.z;
        As[loadCol + 3][loadRow] = av.w;
        Ws[loadCol + 0][loadRow] = wv.x;
        Ws[loadCol + 1][loadRow] = wv.y;
        Ws[loadCol + 2][loadRow] = wv.z;
        Ws[loadCol + 3][loadRow] = wv.w;
        __syncthreads();

#pragma unroll
        for (int kk = 0; kk < GBK; kk++) {
            float a[8], b[8];
            *(float4*)&a[0] = *(const float4*)&As[kk][ty * 8];
            *(float4*)&a[4] = *(const float4*)&As[kk][ty * 8 + 4];
            *(float4*)&b[0] = *(const float4*)&Ws[kk][tx * 8];
            *(float4*)&b[4] = *(const float4*)&Ws[kk][tx * 8 + 4];
#pragma unroll
            for (int i = 0; i < 8; i++)
#pragma unroll
                for (int j = 0; j < 8; j++) acc[i][j] += a[i] * b[j];
        }
        __syncthreads();
    }

    // Epilogue
#pragma unroll
    for (int i = 0; i < 8; i++) {
        const int m = m0 + ty * 8 + i;
        const int bb = m >> 11;       // / SEQ
        const int ss = m & (SEQ - 1);
#pragma unroll
        for (int j = 0; j < 8; j++) {
            const int n = n0 + tx * 8 + j;
            const float v = acc[i][j] + bias[n];
            if (head_split) {
                const int h = n >> 6;
                const int d = n & 63;
                g_dummy_noop: ;
                C[(((size_t)bb * NUM_HEADS + h) * SEQ + ss) * DEPTH + d] = v;
            } else {
                C[(size_t)m * D_MODEL + n] = v;
            }
        }
    }
}

// ---------------------------------------------------------------------------
// Flash attention (causal), fp32.
// One block = (b, h, 128-query tile); one thread = one query row.
// K/V tiles of 32 keys in smem; online softmax; O[64] in registers.
// ---------------------------------------------------------------------------
#define BQ 128
#define BKT 32
#define QS_PITCH 65   // conflict-free scalar column reads

#define ATTN_SMEM_FLOATS (BQ * QS_PITCH + 2 * BKT * DEPTH)
#define ATTN_SMEM_BYTES  (ATTN_SMEM_FLOATS * 4)

__global__ __launch_bounds__(BQ) void attn_kernel(
    const float* __restrict__ Qg, const float* __restrict__ Kg,
    const float* __restrict__ Vg, float* __restrict__ Og)
{
    extern __shared__ float sm[];
    float* Qs = sm;                        // [BQ][QS_PITCH]
    float* Ks = sm + BQ * QS_PITCH;        // [BKT][64]
    float* Vs = Ks + BKT * DEPTH;          // [BKT][64]

    const int tid = threadIdx.x;
    const int b = blockIdx.z;
    const int h = blockIdx.y;
    const int q0 = blockIdx.x * BQ;

    const size_t headOff = (((size_t)b * NUM_HEADS + h) * SEQ) * DEPTH;
    const float* qbase = Qg + headOff;
    const float* kbase = Kg + headOff;
    const float* vbase = Vg + headOff;

    // Load Q tile: 128x64 floats, 64 per thread
    for (int idx = tid; idx < BQ * DEPTH; idx += BQ) {
        const int r = idx >> 6;
        const int c = idx & 63;
        Qs[r * QS_PITCH + c] = qbase[(size_t)(q0 + r) * DEPTH + c];
    }

    const int q = q0 + tid;
    float m = -1e30f, l = 0.f;
    float acc[DEPTH];
#pragma unroll
    for (int d = 0; d < DEPTH; d++) acc[d] = 0.f;

    const int ntiles = (q0 + BQ - 1) / BKT + 1;  // tiles with k0 <= q0+127

    for (int t = 0; t < ntiles; t++) {
        const int k0 = t * BKT;
        __syncthreads();   // previous tile fully consumed (also covers Q load)
        // Load K,V tile: 32x64 each, 16 floats each per thread
        for (int idx = tid; idx < BKT * DEPTH; idx += BQ) {
            Ks[idx] = kbase[(size_t)k0 * DEPTH + idx];
            Vs[idx] = vbase[(size_t)k0 * DEPTH + idx];
        }
        __syncthreads();

        if (k0 <= q) {
            float sc[BKT];
#pragma unroll
            for (int j = 0; j < BKT; j++) sc[j] = 0.f;

            // scores = Q . K  (K reads are warp-uniform -> smem broadcast)
#pragma unroll
            for (int d0 = 0; d0 < DEPTH; d0 += 16) {
                float qr[16];
#pragma unroll
                for (int i = 0; i < 16; i++) qr[i] = Qs[tid * QS_PITCH + d0 + i];
#pragma unroll
                for (int j = 0; j < BKT; j++) {
                    const float4* kp = (const float4*)(Ks + j * DEPTH + d0);
                    const float4 k0v = kp[0], k1v = kp[1], k2v = kp[2], k3v = kp[3];
                    sc[j] += qr[0]  * k0v.x + qr[1]  * k0v.y + qr[2]  * k0v.z + qr[3]  * k0v.w
                           + qr[4]  * k1v.x + qr[5]  * k1v.y + qr[6]  * k1v.z + qr[7]  * k1v.w
                           + qr[8]  * k2v.x + qr[9]  * k2v.y + qr[10] * k2v.z + qr[11] * k2v.w
                           + qr[12] * k3v.x + qr[13] * k3v.y + qr[14] * k3v.z + qr[15] * k3v.w;
                }
            }

            // scale + causal mask + online softmax
            float mt = m;
#pragma unroll
            for (int j = 0; j < BKT; j++) {
                float s = sc[j] * 0.125f;            // 1/sqrt(64)
                if (k0 + j > q) s = -1e30f;
                sc[j] = s;
                mt = fmaxf(mt, s);
            }
            const float scale = __expf(m - mt);
            float lsum = 0.f;
#pragma unroll
            for (int j = 0; j < BKT; j++) {
                const float p = __expf(sc[j] - mt);
                sc[j] = p;
                lsum += p;
            }
            m = mt;
            l = l * scale + lsum;
#pragma unroll
            for (int d = 0; d < DEPTH; d++) acc[d] *= scale;

            // O += P . V  (V reads warp-uniform -> broadcast)
#pragma unroll
            for (int j = 0; j < BKT; j++) {
                const float w = sc[j];
                const float4* vp = (const float4*)(Vs + j * DEPTH);
#pragma unroll
                for (int d4 = 0; d4 < 16; d4++) {
                    const float4 v = vp[d4];
                    acc[d4 * 4 + 0] += w * v.x;
                    acc[d4 * 4 + 1] += w * v.y;
                    acc[d4 * 4 + 2] += w * v.z;
                    acc[d4 * 4 + 3] += w * v.w;
                }
            }
        }
    }

    // Write out in concat layout: [b][q][h*64 + d]
    const float inv = 1.f / l;
    float* outp = Og + ((size_t)b * SEQ + q) * D_MODEL + h * DEPTH;
#pragma unroll
    for (int d4 = 0; d4 < 16; d4++) {
        float4 v;
        v.x = acc[d4 * 4 + 0] * inv;
        v.y = acc[d4 * 4 + 1] * inv;
        v.z = acc[d4 * 4 + 2] * inv;
        v.w = acc[d4 * 4 + 3] * inv;
        *(float4*)(outp + d4 * 4) = v;
    }
}

// ---------------------------------------------------------------------------
// Launch
// ---------------------------------------------------------------------------
extern "C" void kernel_launch(void* const* d_in, const int* in_sizes, int n_in,
                              void* d_out, int out_size)
{
    const float* v       = (const float*)d_in[0];
    const float* k       = (const float*)d_in[1];
    const float* q       = (const float*)d_in[2];
    // d_in[3] = mask (causal triu) -- implemented analytically in attn_kernel
    const float* wq_w    = (const float*)d_in[4];
    const float* wq_b    = (const float*)d_in[5];
    const float* wk_w    = (const float*)d_in[6];
    const float* wk_b    = (const float*)d_in[7];
    const float* wv_w    = (const float*)d_in[8];
    const float* wv_b    = (const float*)d_in[9];
    const float* dense_w = (const float*)d_in[10];
    const float* dense_b = (const float*)d_in[11];
    float* out = (float*)d_out;

    float *qh, *kh, *vh, *att;
    cudaGetSymbolAddress((void**)&qh,  g_qh);
    cudaGetSymbolAddress((void**)&kh,  g_kh);
    cudaGetSymbolAddress((void**)&vh,  g_vh);
    cudaGetSymbolAddress((void**)&att, g_att);

    cudaFuncSetAttribute(attn_kernel,
                         cudaFuncAttributeMaxDynamicSharedMemorySize,
                         ATTN_SMEM_BYTES);

    const dim3 ggrid(D_MODEL / GBN, M_ROWS / GBM);  // (8, 32)
    const dim3 gblock(256);

    gemm_bias_kernel<<<ggrid, gblock>>>(q, wq_w, wq_b, qh, 1);
    gemm_bias_kernel<<<ggrid, gblock>>>(k, wk_w, wk_b, kh, 1);
    gemm_bias_kernel<<<ggrid, gblock>>>(v, wv_w, wv_b, vh, 1);

    const dim3 agrid(SEQ / BQ, NUM_HEADS, BATCH);   // (16, 16, 2)
    attn_kernel<<<agrid, BQ, ATTN_SMEM_BYTES>>>(qh, kh, vh, att);

    gemm_bias_kernel<<<ggrid, gblock>>>(att, dense_w, dense_b, out, 0);
}

// round 2
// speedup vs baseline: 2.5381x; 2.5381x over previous
#include <cuda_runtime.h>
#include <cstddef>
#include <cstdint>

#define D_MODEL   1024
#define NUM_HEADS 16
#define DEPTH     64
#define BATCH     2
#define SEQ       2048
#define M_ROWS    (BATCH * SEQ)   // 4096

// ---------------------------------------------------------------------------
// Scratch
// ---------------------------------------------------------------------------
__device__ float g_qh[BATCH * NUM_HEADS * SEQ * DEPTH];   // [B,H,S,64]
__device__ float g_kh[BATCH * NUM_HEADS * SEQ * DEPTH];
__device__ float g_vh[BATCH * NUM_HEADS * SEQ * DEPTH];
__device__ float g_att[BATCH * SEQ * D_MODEL];            // [B,S,H*64]

// ---------------------------------------------------------------------------
// tf32 helpers
// ---------------------------------------------------------------------------
__device__ __forceinline__ unsigned f2tf(float f) {
    unsigned u;
    asm("cvt.rna.tf32.f32 %0, %1;" : "=r"(u) : "f"(f));
    return u;
}

__device__ __forceinline__ void mma8(float* c, const unsigned* a, const unsigned* b) {
    asm volatile(
        "mma.sync.aligned.m16n8k8.row.col.f32.tf32.tf32.f32 "
        "{%0,%1,%2,%3},{%4,%5,%6,%7},{%8,%9},{%0,%1,%2,%3};"
        : "+f"(c[0]), "+f"(c[1]), "+f"(c[2]), "+f"(c[3])
        : "r"(a[0]), "r"(a[1]), "r"(a[2]), "r"(a[3]), "r"(b[0]), "r"(b[1]));
}

// ---------------------------------------------------------------------------
// tf32 GEMM: C = A(M,K) @ W^T(N,K) + bias.  M=4096, N=K=1024.
// Block 128x128, BK=16, 256 threads, warps 2(m)x4(n), warp tile 64x32.
// Smem holds fragment-native layouts: conflict-free LDS.128 / LDS.64.
// ---------------------------------------------------------------------------
__global__ __launch_bounds__(256) void gemm_tf32(
    const float* __restrict__ A, const float* __restrict__ W,
    const float* __restrict__ bias, float* __restrict__ C, int head_split)
{
    __shared__ uint4 AsfV[2][8][32];    // [ktile][m16tile][lane] -> a0..a3
    __shared__ uint2 BsfV[2][16][32];   // [ktile][n8tile][lane] -> b0,b1

    const int tid  = threadIdx.x;
    const int lane = tid & 31;
    const int w    = tid >> 5;
    const int wm   = w >> 2;            // 0..1
    const int wn   = w & 3;             // 0..3
    const int m0   = blockIdx.y * 128;
    const int n0   = blockIdx.x * 128;

    float acc[4][4][4];
#pragma unroll
    for (int i = 0; i < 4; i++)
#pragma unroll
        for (int j = 0; j < 4; j++)
#pragma unroll
            for (int e = 0; e < 4; e++) acc[i][j][e] = 0.f;

    const int lrow = tid >> 1;           // 0..127
    const int lcol = (tid & 1) * 8;      // 0 or 8
    const int ktS  = tid & 1;            // which k-tile this thread stages
    const float* Ap = A + (size_t)(m0 + lrow) * D_MODEL + lcol;
    const float* Wp = W + (size_t)(n0 + lrow) * D_MODEL + lcol;

    float4 ra0 = *(const float4*)(Ap);
    float4 ra1 = *(const float4*)(Ap + 4);
    float4 rb0 = *(const float4*)(Wp);
    float4 rb1 = *(const float4*)(Wp + 4);

    const int r    = lrow & 15;          // row within m16 tile
    const int mt   = lrow >> 4;
    const int rbit = (r >> 3) & 1;
    const int cB   = lrow & 7;           // col within n8 tile
    const int nt   = lrow >> 3;

    for (int k0 = 0; k0 < D_MODEL; k0 += 16) {
        // stage regs -> smem in fragment layout (with tf32 rounding)
        {
            float av[8] = {ra0.x, ra0.y, ra0.z, ra0.w, ra1.x, ra1.y, ra1.z, ra1.w};
            float bv[8] = {rb0.x, rb0.y, rb0.z, rb0.w, rb1.x, rb1.y, rb1.z, rb1.w};
            unsigned* dstA = (unsigned*)&AsfV[ktS][mt][0];
            unsigned* dstB = (unsigned*)&BsfV[ktS][nt][0];
#pragma unroll
            for (int u = 0; u < 8; u++) {
                const int laneA = (r & 7) * 4 + (u & 3);
                const int regA  = rbit + ((u >> 2) & 1) * 2;
                dstA[laneA * 4 + regA] = f2tf(av[u]);
                const int laneB = cB * 4 + (u & 3);
                const int regB  = (u >> 2) & 1;
                dstB[laneB * 2 + regB] = f2tf(bv[u]);
            }
        }
        __syncthreads();

        if (k0 + 16 < D_MODEL) {
            ra0 = *(const float4*)(Ap + k0 + 16);
            ra1 = *(const float4*)(Ap + k0 + 20);
            rb0 = *(const float4*)(Wp + k0 + 16);
            rb1 = *(const float4*)(Wp + k0 + 20);
        }

#pragma unroll
        for (int kt = 0; kt < 2; kt++) {
            unsigned af[4][4], bf[4][2];
#pragma unroll
            for (int i = 0; i < 4; i++) {
                uint4 a4 = AsfV[kt][wm * 4 + i][lane];
                af[i][0] = a4.x; af[i][1] = a4.y; af[i][2] = a4.z; af[i][3] = a4.w;
            }
#pragma unroll
            for (int j = 0; j < 4; j++) {
                uint2 b2 = BsfV[kt][wn * 4 + j][lane];
                bf[j][0] = b2.x; bf[j][1] = b2.y;
            }
#pragma unroll
            for (int i = 0; i < 4; i++)
#pragma unroll
                for (int j = 0; j < 4; j++) mma8(acc[i][j], af[i], bf[j]);
        }
        __syncthreads();
    }

    // epilogue
#pragma unroll
    for (int i = 0; i < 4; i++) {
#pragma unroll
        for (int j = 0; j < 4; j++) {
            const int m = m0 + wm * 64 + i * 16 + (lane >> 2);
            const int n = n0 + wn * 32 + j * 8 + 2 * (lane & 3);
            const float2 bb = *(const float2*)(bias + n);
            float2 v0, v1;
            v0.x = acc[i][j][0] + bb.x; v0.y = acc[i][j][1] + bb.y;
            v1.x = acc[i][j][2] + bb.x; v1.y = acc[i][j][3] + bb.y;
            if (head_split) {
                const int h = n >> 6, d = n & 63;
                const int b0r = m >> 11, s0r = m & (SEQ - 1);
                const int b1r = (m + 8) >> 11, s1r = (m + 8) & (SEQ - 1);
                *(float2*)&C[(((size_t)b0r * NUM_HEADS + h) * SEQ + s0r) * DEPTH + d] = v0;
                *(float2*)&C[(((size_t)b1r * NUM_HEADS + h) * SEQ + s1r) * DEPTH + d] = v1;
            } else {
                *(float2*)&C[(size_t)m * D_MODEL + n] = v0;
                *(float2*)&C[(size_t)(m + 8) * D_MODEL + n] = v1;
            }
        }
    }
}

// ---------------------------------------------------------------------------
// FA2-style causal attention with tf32 mma.
// Block: 128 threads (4 warps), 64 queries (16 rows/warp), 64-key tiles.
// Smem (dynamic, 48KB): Kf (B-frags for QK^T), Vf (B-frags for PV),
//                       Pf (warp-private A-frags for P).
// ---------------------------------------------------------------------------
#define ATTN_SMEM_BYTES 49152

// offsets in unsigned units
#define KF_PTR(ash, dt, kt2, l)  ((ash) + ((((dt) * 8 + (kt2)) * 32 + (l)) * 2))
#define VF_PTR(ash, kt2, dt, l)  ((ash) + 4096 + ((((kt2) * 8 + (dt)) * 32 + (l)) * 2))
#define PF_PTR(ash, ww, kt2, l)  ((ash) + 8192 + ((((ww) * 8 + (kt2)) * 32 + (l)) * 4))

__global__ __launch_bounds__(128) void attn_tf32(
    const float* __restrict__ Qg, const float* __restrict__ Kg,
    const float* __restrict__ Vg, float* __restrict__ Og)
{
    extern __shared__ unsigned ash[];

    const int tid  = threadIdx.x;
    const int lane = tid & 31;
    const int w    = tid >> 5;
    const int b    = blockIdx.z;
    const int h    = blockIdx.y;
    const int q0   = blockIdx.x * 64;

    const size_t hoff = ((size_t)(b * NUM_HEADS + h) * SEQ) * DEPTH;
    const float* kb = Kg + hoff;
    const float* vb = Vg + hoff;

    const int r0 = lane >> 2;   // 0..7
    const int c0 = lane & 3;    // 0..3

    // Q fragments (A operand), loaded once from global, tf32-rounded
    unsigned qa[8][4];
    {
        const float* qbase = Qg + hoff + (size_t)(q0 + w * 16) * DEPTH;
#pragma unroll
        for (int kt = 0; kt < 8; kt++) {
            qa[kt][0] = f2tf(qbase[(size_t)(r0)     * DEPTH + kt * 8 + c0]);
            qa[kt][1] = f2tf(qbase[(size_t)(r0 + 8) * DEPTH + kt * 8 + c0]);
            qa[kt][2] = f2tf(qbase[(size_t)(r0)     * DEPTH + kt * 8 + c0 + 4]);
            qa[kt][3] = f2tf(qbase[(size_t)(r0 + 8) * DEPTH + kt * 8 + c0 + 4]);
        }
    }

    float o[8][4];
#pragma unroll
    for (int j = 0; j < 8; j++)
#pragma unroll
        for (int e = 0; e < 4; e++) o[j][e] = 0.f;
    float m0r = -1e30f, m1r = -1e30f;
    float l0r = 0.f,    l1r = 0.f;

    const int ntile = q0 / 64 + 1;

    for (int t = 0; t < ntile; t++) {
        __syncthreads();
        // load K,V 64x64 tiles into fragment-layout smem
        for (int f = tid; f < 1024; f += 128) {      // float4 granularity
            const int key   = f >> 4;
            const int dbase = (f & 15) * 4;
            const float4 kv = *(const float4*)(kb + (size_t)(t * 64 + key) * DEPTH + dbase);
            const float4 vv = *(const float4*)(vb + (size_t)(t * 64 + key) * DEPTH + dbase);
            const float kvf[4] = {kv.x, kv.y, kv.z, kv.w};
            const float vvf[4] = {vv.x, vv.y, vv.z, vv.w};
#pragma unroll
            for (int u = 0; u < 4; u++) {
                const int d = dbase + u;
                // Kf: B-frag of K^T, k-dim = depth, n-dim = key
                KF_PTR(ash, d >> 3, key >> 3, (key & 7) * 4 + (d & 3))[(d >> 2) & 1] = f2tf(kvf[u]);
                // Vf: B-frag of V, k-dim = key, n-dim = depth
                VF_PTR(ash, key >> 3, d >> 3, (d & 7) * 4 + (key & 3))[(key >> 2) & 1] = f2tf(vvf[u]);
            }
        }
        __syncthreads();

        // S = Q @ K^T  (warp tile: 16 x 64)
        float s[8][4];
#pragma unroll
        for (int j = 0; j < 8; j++) {
#pragma unroll
            for (int e = 0; e < 4; e++) s[j][e] = 0.f;
#pragma unroll
            for (int kt = 0; kt < 8; kt++) {
                const uint2 b2 = *(const uint2*)KF_PTR(ash, kt, j, lane);
                unsigned bf[2] = {b2.x, b2.y};
                mma8(s[j], qa[kt], bf);
            }
        }

        // scale + causal mask (only diagonal tile) + row maxes
        const bool diag = (t == ntile - 1);
        const int qrow = q0 + w * 16 + r0;
        float mx0 = -1e30f, mx1 = -1e30f;
#pragma unroll
        for (int j = 0; j < 8; j++) {
#pragma unroll
            for (int e = 0; e < 4; e++) {
                float v = s[j][e] * 0.125f;
                if (diag) {
                    const int key = t * 64 + j * 8 + 2 * (lane & 3) + (e & 1);
                    const int qq  = qrow + ((e >> 1) << 3);
                    if (key > qq) v = -1e30f;
                }
                s[j][e] = v;
            }
            mx0 = fmaxf(mx0, fmaxf(s[j][0], s[j][1]));
            mx1 = fmaxf(mx1, fmaxf(s[j][2], s[j][3]));
        }
        mx0 = fmaxf(mx0, __shfl_xor_sync(0xffffffffu, mx0, 1));
        mx0 = fmaxf(mx0, __shfl_xor_sync(0xffffffffu, mx0, 2));
        mx1 = fmaxf(mx1, __shfl_xor_sync(0xffffffffu, mx1, 1));
        mx1 = fmaxf(mx1, __shfl_xor_sync(0xffffffffu, mx1, 2));

        const float mn0 = fmaxf(m0r, mx0);
        const float mn1 = fmaxf(m1r, mx1);
        const float al0 = __expf(m0r - mn0);
        const float al1 = __expf(m1r - mn1);

        float ls0 = 0.f, ls1 = 0.f;
#pragma unroll
        for (int j = 0; j < 8; j++) {
            s[j][0] = __expf(s[j][0] - mn0); ls0 += s[j][0];
            s[j][1] = __expf(s[j][1] - mn0); ls0 += s[j][1];
            s[j][2] = __expf(s[j][2] - mn1); ls1 += s[j][2];
            s[j][3] = __expf(s[j][3] - mn1); ls1 += s[j][3];
        }
        ls0 += __shfl_xor_sync(0xffffffffu, ls0, 1);
        ls0 += __shfl_xor_sync(0xffffffffu, ls0, 2);
        ls1 += __shfl_xor_sync(0xffffffffu, ls1, 1);
        ls1 += __shfl_xor_sync(0xffffffffu, ls1, 2);

        l0r = l0r * al0 + ls0;
        l1r = l1r * al1 + ls1;
        m0r = mn0; m1r = mn1;

#pragma unroll
        for (int j = 0; j < 8; j++) {
            o[j][0] *= al0; o[j][1] *= al0;
            o[j][2] *= al1; o[j][3] *= al1;
        }

        // store P (C-frag) -> warp-private smem as A-frag layout
        __syncwarp();
#pragma unroll
        for (int j = 0; j < 8; j++) {
#pragma unroll
            for (int e = 0; e < 4; e++) {
                const int cc = 2 * (lane & 3) + (e & 1);     // col within j-tile
                const int rr = r0 + ((e >> 1) << 3);          // row within warp tile
                PF_PTR(ash, w, j, (rr & 7) * 4 + (cc & 3))[((rr >> 3) & 1) + ((cc >> 2) & 1) * 2]
                    = f2tf(s[j][e]);
            }
        }
        __syncwarp();

        // O += P @ V
#pragma unroll
        for (int kt = 0; kt < 8; kt++) {
            const uint4 a4 = *(const uint4*)PF_PTR(ash, w, kt, lane);
            unsigned af[4] = {a4.x, a4.y, a4.z, a4.w};
#pragma unroll
            for (int j = 0; j < 8; j++) {
                const uint2 b2 = *(const uint2*)VF_PTR(ash, kt, j, lane);
                unsigned bf[2] = {b2.x, b2.y};
                mma8(o[j], af, bf);
            }
        }
    }

    // epilogue: normalize & write concat layout [b][q][h*64 + col]
    const float inv0 = 1.f / l0r;
    const float inv1 = 1.f / l1r;
    const int qq = q0 + w * 16 + r0;
#pragma unroll
    for (int j = 0; j < 8; j++) {
        const int col = j * 8 + 2 * (lane & 3);
        float2 v0, v1;
        v0.x = o[j][0] * inv0; v0.y = o[j][1] * inv0;
        v1.x = o[j][2] * inv1; v1.y = o[j][3] * inv1;
        *(float2*)&Og[((size_t)(b * SEQ + qq))     * D_MODEL + h * DEPTH + col] = v0;
        *(float2*)&Og[((size_t)(b * SEQ + qq + 8)) * D_MODEL + h * DEPTH + col] = v1;
    }
}

// ---------------------------------------------------------------------------
// Launch
// ---------------------------------------------------------------------------
extern "C" void kernel_launch(void* const* d_in, const int* in_sizes, int n_in,
                              void* d_out, int out_size)
{
    const float* v       = (const float*)d_in[0];
    const float* k       = (const float*)d_in[1];
    const float* q       = (const float*)d_in[2];
    // d_in[3] = mask (causal triu) -- analytic in attn kernel
    const float* wq_w    = (const float*)d_in[4];
    const float* wq_b    = (const float*)d_in[5];
    const float* wk_w    = (const float*)d_in[6];
    const float* wk_b    = (const float*)d_in[7];
    const float* wv_w    = (const float*)d_in[8];
    const float* wv_b    = (const float*)d_in[9];
    const float* dense_w = (const float*)d_in[10];
    const float* dense_b = (const float*)d_in[11];
    float* out = (float*)d_out;

    float *qh, *kh, *vh, *att;
    cudaGetSymbolAddress((void**)&qh,  g_qh);
    cudaGetSymbolAddress((void**)&kh,  g_kh);
    cudaGetSymbolAddress((void**)&vh,  g_vh);
    cudaGetSymbolAddress((void**)&att, g_att);

    cudaFuncSetAttribute(attn_tf32,
                         cudaFuncAttributeMaxDynamicSharedMemorySize,
                         ATTN_SMEM_BYTES);

    const dim3 ggrid(D_MODEL / 128, M_ROWS / 128);   // (8, 32)

    gemm_tf32<<<ggrid, 256>>>(q, wq_w, wq_b, qh, 1);
    gemm_tf32<<<ggrid, 256>>>(k, wk_w, wk_b, kh, 1);
    gemm_tf32<<<ggrid, 256>>>(v, wv_w, wv_b, vh, 1);

    const dim3 agrid(SEQ / 64, NUM_HEADS, BATCH);    // (32, 16, 2)
    attn_tf32<<<agrid, 128, ATTN_SMEM_BYTES>>>(qh, kh, vh, att);

    gemm_tf32<<<ggrid, 256>>>(att, dense_w, dense_b, out, 0);
}

// round 3
// speedup vs baseline: 3.8694x; 1.5245x over previous
#include <cuda_runtime.h>
#include <cstddef>
#include <cstdint>

#define D_MODEL   1024
#define NUM_HEADS 16
#define DEPTH     64
#define BATCH     2
#define SEQ       2048
#define M_ROWS    (BATCH * SEQ)   // 4096

// ---------------------------------------------------------------------------
// Scratch
// ---------------------------------------------------------------------------
__device__ float g_qh[BATCH * NUM_HEADS * SEQ * DEPTH];   // [B,H,S,64]
__device__ float g_kh[BATCH * NUM_HEADS * SEQ * DEPTH];
__device__ float g_vh[BATCH * NUM_HEADS * SEQ * DEPTH];
__device__ float g_att[BATCH * SEQ * D_MODEL];            // [B,S,H*64]

// ---------------------------------------------------------------------------
// tf32 helpers
// ---------------------------------------------------------------------------
__device__ __forceinline__ unsigned f2tf(float f) {
    unsigned u;
    asm("cvt.rna.tf32.f32 %0, %1;" : "=r"(u) : "f"(f));
    return u;
}

__device__ __forceinline__ void mma8(float* c, const unsigned* a, const unsigned* b) {
    asm volatile(
        "mma.sync.aligned.m16n8k8.row.col.f32.tf32.tf32.f32 "
        "{%0,%1,%2,%3},{%4,%5,%6,%7},{%8,%9},{%0,%1,%2,%3};"
        : "+f"(c[0]), "+f"(c[1]), "+f"(c[2]), "+f"(c[3])
        : "r"(a[0]), "r"(a[1]), "r"(a[2]), "r"(a[3]), "r"(b[0]), "r"(b[1]));
}

// ---------------------------------------------------------------------------
// tf32 GEMM core: C = A(M,K) @ W^T(N,K) + bias.  M=4096, N=K=1024.
// Block 128x128, BK=16, 256 threads, warps 2(m)x4(n), warp tile 64x32.
// Fragment-native smem with fully vectorized staging (STS.128).
//   A smem: [2 kt][8 mt][2 rbit][32 lane x 2 khigh]   (2048 u)
//   B smem: [2 kt][16 nt][32 lane x 2 reg]            (2048 u)
// ---------------------------------------------------------------------------
__device__ __forceinline__ void gemm_core(
    const float* __restrict__ A, const float* __restrict__ W,
    const float* __restrict__ bias, float* __restrict__ C, int head_split,
    int m0, int n0)
{
    __shared__ __align__(16) unsigned As[2048];
    __shared__ __align__(16) unsigned Bs[2048];

    const int tid  = threadIdx.x;
    const int lane = tid & 31;
    const int w    = tid >> 5;
    const int wm   = w >> 2;
    const int wn   = w & 3;

    float acc[4][4][4];
#pragma unroll
    for (int i = 0; i < 4; i++)
#pragma unroll
        for (int j = 0; j < 4; j++)
#pragma unroll
            for (int e = 0; e < 4; e++) acc[i][j][e] = 0.f;

    const int lrow = tid >> 1;           // 0..127
    const int lcol = (tid & 1) * 8;      // 0 or 8
    const int ktS  = tid & 1;            // staged k-tile
    const float* Ap = A + (size_t)(m0 + lrow) * D_MODEL + lcol;
    const float* Wp = W + (size_t)(n0 + lrow) * D_MODEL + lcol;

    float4 ra0 = *(const float4*)(Ap);
    float4 ra1 = *(const float4*)(Ap + 4);
    float4 rb0 = *(const float4*)(Wp);
    float4 rb1 = *(const float4*)(Wp + 4);

    const int r    = lrow & 15;
    const int mt   = lrow >> 4;
    const int rbit = (r >> 3) & 1;
    const int nt   = lrow >> 3;
    unsigned* dA = As + (((ktS * 8 + mt) * 2 + rbit) * 64) + (r & 7) * 8;
    unsigned* dB = Bs + (((ktS * 16 + nt) * 32) + (lrow & 7) * 4) * 2;

    for (int k0 = 0; k0 < D_MODEL; k0 += 16) {
        uint4 s0, s1;
        s0.x = f2tf(ra0.x); s0.y = f2tf(ra1.x); s0.z = f2tf(ra0.y); s0.w = f2tf(ra1.y);
        s1.x = f2tf(ra0.z); s1.y = f2tf(ra1.z); s1.z = f2tf(ra0.w); s1.w = f2tf(ra1.w);
        ((uint4*)dA)[0] = s0;
        ((uint4*)dA)[1] = s1;
        s0.x = f2tf(rb0.x); s0.y = f2tf(rb1.x); s0.z = f2tf(rb0.y); s0.w = f2tf(rb1.y);
        s1.x = f2tf(rb0.z); s1.y = f2tf(rb1.z); s1.z = f2tf(rb0.w); s1.w = f2tf(rb1.w);
        ((uint4*)dB)[0] = s0;
        ((uint4*)dB)[1] = s1;
        __syncthreads();

        if (k0 + 16 < D_MODEL) {
            ra0 = *(const float4*)(Ap + k0 + 16);
            ra1 = *(const float4*)(Ap + k0 + 20);
            rb0 = *(const float4*)(Wp + k0 + 16);
            rb1 = *(const float4*)(Wp + k0 + 20);
        }

#pragma unroll
        for (int kt = 0; kt < 2; kt++) {
            unsigned af[4][4], bf[4][2];
#pragma unroll
            for (int i = 0; i < 4; i++) {
                const unsigned base = (kt * 8 + wm * 4 + i) * 2;
                uint2 lo = ((const uint2*)(As + (base + 0) * 64))[lane];
                uint2 hi = ((const uint2*)(As + (base + 1) * 64))[lane];
                af[i][0] = lo.x; af[i][1] = hi.x; af[i][2] = lo.y; af[i][3] = hi.y;
            }
#pragma unroll
            for (int j = 0; j < 4; j++) {
                uint2 b2 = ((const uint2*)(Bs + (kt * 16 + wn * 4 + j) * 64))[lane];
                bf[j][0] = b2.x; bf[j][1] = b2.y;
            }
#pragma unroll
            for (int i = 0; i < 4; i++)
#pragma unroll
                for (int j = 0; j < 4; j++) mma8(acc[i][j], af[i], bf[j]);
        }
        __syncthreads();
    }

    // epilogue
#pragma unroll
    for (int i = 0; i < 4; i++) {
#pragma unroll
        for (int j = 0; j < 4; j++) {
            const int m = m0 + wm * 64 + i * 16 + (lane >> 2);
            const int n = n0 + wn * 32 + j * 8 + 2 * (lane & 3);
            const float2 bb = *(const float2*)(bias + n);
            float2 v0, v1;
            v0.x = acc[i][j][0] + bb.x; v0.y = acc[i][j][1] + bb.y;
            v1.x = acc[i][j][2] + bb.x; v1.y = acc[i][j][3] + bb.y;
            if (head_split) {
                const int h = n >> 6, d = n & 63;
                const int b0r = m >> 11, s0r = m & (SEQ - 1);
                const int b1r = (m + 8) >> 11, s1r = (m + 8) & (SEQ - 1);
                *(float2*)&C[(((size_t)b0r * NUM_HEADS + h) * SEQ + s0r) * DEPTH + d] = v0;
                *(float2*)&C[(((size_t)b1r * NUM_HEADS + h) * SEQ + s1r) * DEPTH + d] = v1;
            } else {
                *(float2*)&C[(size_t)m * D_MODEL + n] = v0;
                *(float2*)&C[(size_t)(m + 8) * D_MODEL + n] = v1;
            }
        }
    }
}

__global__ __launch_bounds__(256) void gemm_qkv(
    const float* __restrict__ q, const float* __restrict__ k, const float* __restrict__ v,
    const float* __restrict__ wq, const float* __restrict__ bq,
    const float* __restrict__ wk, const float* __restrict__ bk,
    const float* __restrict__ wv, const float* __restrict__ bv,
    float* __restrict__ qh, float* __restrict__ kh, float* __restrict__ vh)
{
    const int z = blockIdx.z;
    const float* A = (z == 0) ? q : (z == 1) ? k : v;
    const float* W = (z == 0) ? wq : (z == 1) ? wk : wv;
    const float* B = (z == 0) ? bq : (z == 1) ? bk : bv;
    float*       C = (z == 0) ? qh : (z == 1) ? kh : vh;
    gemm_core(A, W, B, C, 1, blockIdx.y * 128, blockIdx.x * 128);
}

__global__ __launch_bounds__(256) void gemm_dense(
    const float* __restrict__ A, const float* __restrict__ W,
    const float* __restrict__ bias, float* __restrict__ C)
{
    gemm_core(A, W, bias, C, 0, blockIdx.y * 128, blockIdx.x * 128);
}

// ---------------------------------------------------------------------------
// FA2-style causal attention, tf32 mma.
// Block: 256 threads (8 warps), 128 queries (16 rows/warp), 64-key tiles.
// Pairing: block bx handles q-tiles bx and 15-bx -> uniform 34 tile-iters.
// Smem (64KB dynamic, unsigned units):
//   Kf [8 dt][8 kt2][32 lane][2]   0..4095
//   Vf [8 kt2][8 dt][32 lane][2]   4096..8191
//   Pf [8 w][8 kt][32 lane][4]     8192..16383
// ---------------------------------------------------------------------------
#define ATTN_THREADS 256
#define ATTN_SMEM_BYTES 65536

__global__ __launch_bounds__(ATTN_THREADS, 2) void attn_tf32(
    const float* __restrict__ Qg, const float* __restrict__ Kg,
    const float* __restrict__ Vg, float* __restrict__ Og)
{
    extern __shared__ unsigned ash[];

    const int tid  = threadIdx.x;
    const int lane = tid & 31;
    const int w    = tid >> 5;
    const int b    = blockIdx.z;
    const int h    = blockIdx.y;

    const size_t hoff = ((size_t)(b * NUM_HEADS + h) * SEQ) * DEPTH;
    const float* kb = Kg + hoff;
    const float* vb = Vg + hoff;

    const int r0 = lane >> 2;
    const int c0 = lane & 3;

#pragma unroll 1
    for (int pass = 0; pass < 2; pass++) {
        const int p  = pass ? (15 - (int)blockIdx.x) : (int)blockIdx.x;
        const int q0 = p * 128;

        // Q fragments (A operand)
        unsigned qa[8][4];
        {
            const float* qbase = Qg + hoff + (size_t)(q0 + w * 16) * DEPTH;
#pragma unroll
            for (int kt = 0; kt < 8; kt++) {
                qa[kt][0] = f2tf(qbase[(size_t)(r0)     * DEPTH + kt * 8 + c0]);
                qa[kt][1] = f2tf(qbase[(size_t)(r0 + 8) * DEPTH + kt * 8 + c0]);
                qa[kt][2] = f2tf(qbase[(size_t)(r0)     * DEPTH + kt * 8 + c0 + 4]);
                qa[kt][3] = f2tf(qbase[(size_t)(r0 + 8) * DEPTH + kt * 8 + c0 + 4]);
            }
        }

        float o[8][4];
#pragma unroll
        for (int j = 0; j < 8; j++)
#pragma unroll
            for (int e = 0; e < 4; e++) o[j][e] = 0.f;
        float m0r = -1e30f, m1r = -1e30f;
        float l0r = 0.f,    l1r = 0.f;

        const int ntile = 2 * p + 2;
        const int qhiW  = q0 + w * 16 + 15;   // max query row of this warp

        for (int t = 0; t < ntile; t++) {
            __syncthreads();
            // ---- stage K (vectorized: 2 x STS.128 per 8-float chunk) ----
            for (int c = tid; c < 512; c += ATTN_THREADS) {
                const int key = c >> 3;
                const int kt  = c & 7;
                const float* src = kb + (size_t)(t * 64 + key) * DEPTH + kt * 8;
                const float4 a0 = *(const float4*)(src);
                const float4 a1 = *(const float4*)(src + 4);
                unsigned* dst = ash + ((kt * 8 + (key >> 3)) * 32 + (key & 7) * 4) * 2;
                uint4 s0, s1;
                s0.x = f2tf(a0.x); s0.y = f2tf(a1.x); s0.z = f2tf(a0.y); s0.w = f2tf(a1.y);
                s1.x = f2tf(a0.z); s1.y = f2tf(a1.z); s1.z = f2tf(a0.w); s1.w = f2tf(a1.w);
                ((uint4*)dst)[0] = s0;
                ((uint4*)dst)[1] = s1;
            }
            // ---- stage V (paired rows: 4 x STS.64 per unit) ----
            for (int u = tid; u < 512; u += ATTN_THREADS) {
                const int kg = u >> 6;         // key group of 8
                const int kl = (u >> 4) & 3;
                const int dc = u & 15;         // d chunk of 4
                const int keyA = kg * 8 + kl;
                const float4 va = *(const float4*)(vb + (size_t)(t * 64 + keyA)     * DEPTH + dc * 4);
                const float4 vB = *(const float4*)(vb + (size_t)(t * 64 + keyA + 4) * DEPTH + dc * 4);
                unsigned* dst = ash + 4096 + ((kg * 8 + (dc >> 1)) * 32 + (dc & 1) * 16 + kl) * 2;
                uint2 p0; p0.x = f2tf(va.x); p0.y = f2tf(vB.x); *(uint2*)(dst + 0)  = p0;
                uint2 p1; p1.x = f2tf(va.y); p1.y = f2tf(vB.y); *(uint2*)(dst + 8)  = p1;
                uint2 p2; p2.x = f2tf(va.z); p2.y = f2tf(vB.z); *(uint2*)(dst + 16) = p2;
                uint2 p3; p3.x = f2tf(va.w); p3.y = f2tf(vB.w); *(uint2*)(dst + 24) = p3;
            }
            __syncthreads();

            if (t * 64 > qhiW) continue;   // warp tile fully masked

            // ---- S = Q @ K^T ----
            float s[8][4];
#pragma unroll
            for (int j = 0; j < 8; j++) {
#pragma unroll
                for (int e = 0; e < 4; e++) s[j][e] = 0.f;
#pragma unroll
                for (int kt = 0; kt < 8; kt++) {
                    const uint2 b2 = ((const uint2*)(ash + (kt * 8 + j) * 64))[lane];
                    unsigned bf[2] = {b2.x, b2.y};
                    mma8(s[j], qa[kt], bf);
                }
            }

            // ---- scale + causal mask + online softmax ----
            const bool diag = (t >= ntile - 2);
            const int qrow = q0 + w * 16 + r0;
            float mx0 = -1e30f, mx1 = -1e30f;
#pragma unroll
            for (int j = 0; j < 8; j++) {
#pragma unroll
                for (int e = 0; e < 4; e++) {
                    float vv = s[j][e] * 0.125f;
                    if (diag) {
                        const int key = t * 64 + j * 8 + 2 * (lane & 3) + (e & 1);
                        const int qq  = qrow + ((e >> 1) << 3);
                        if (key > qq) vv = -1e30f;
                    }
                    s[j][e] = vv;
                }
                mx0 = fmaxf(mx0, fmaxf(s[j][0], s[j][1]));
                mx1 = fmaxf(mx1, fmaxf(s[j][2], s[j][3]));
            }
            mx0 = fmaxf(mx0, __shfl_xor_sync(0xffffffffu, mx0, 1));
            mx0 = fmaxf(mx0, __shfl_xor_sync(0xffffffffu, mx0, 2));
            mx1 = fmaxf(mx1, __shfl_xor_sync(0xffffffffu, mx1, 1));
            mx1 = fmaxf(mx1, __shfl_xor_sync(0xffffffffu, mx1, 2));

            const float mn0 = fmaxf(m0r, mx0);
            const float mn1 = fmaxf(m1r, mx1);
            const float al0 = __expf(m0r - mn0);
            const float al1 = __expf(m1r - mn1);

            float ls0 = 0.f, ls1 = 0.f;
#pragma unroll
            for (int j = 0; j < 8; j++) {
                s[j][0] = __expf(s[j][0] - mn0); ls0 += s[j][0];
                s[j][1] = __expf(s[j][1] - mn0); ls0 += s[j][1];
                s[j][2] = __expf(s[j][2] - mn1); ls1 += s[j][2];
                s[j][3] = __expf(s[j][3] - mn1); ls1 += s[j][3];
            }
            ls0 += __shfl_xor_sync(0xffffffffu, ls0, 1);
            ls0 += __shfl_xor_sync(0xffffffffu, ls0, 2);
            ls1 += __shfl_xor_sync(0xffffffffu, ls1, 1);
            ls1 += __shfl_xor_sync(0xffffffffu, ls1, 2);

            l0r = l0r * al0 + ls0;
            l1r = l1r * al1 + ls1;
            m0r = mn0; m1r = mn1;

#pragma unroll
            for (int j = 0; j < 8; j++) {
                o[j][0] *= al0; o[j][1] *= al0;
                o[j][2] *= al1; o[j][3] *= al1;
            }

            // ---- P (C-frag) -> warp-private smem as A-frag layout ----
            __syncwarp();
#pragma unroll
            for (int j = 0; j < 8; j++) {
#pragma unroll
                for (int e = 0; e < 4; e++) {
                    const int cc = 2 * (lane & 3) + (e & 1);
                    const int rr = r0 + ((e >> 1) << 3);
                    ash[8192 + ((w * 8 + j) * 32 + (rr & 7) * 4 + (cc & 3)) * 4
                        + ((rr >> 3) & 1) + ((cc >> 2) & 1) * 2] = f2tf(s[j][e]);
                }
            }
            __syncwarp();

            // ---- O += P @ V ----
#pragma unroll
            for (int kt = 0; kt < 8; kt++) {
                const uint4 a4 = ((const uint4*)(ash + 8192 + (w * 8 + kt) * 128))[lane];
                unsigned af[4] = {a4.x, a4.y, a4.z, a4.w};
#pragma unroll
                for (int j = 0; j < 8; j++) {
                    const uint2 b2 = ((const uint2*)(ash + 4096 + (kt * 8 + j) * 64))[lane];
                    unsigned bf[2] = {b2.x, b2.y};
                    mma8(o[j], af, bf);
                }
            }
        }

        // ---- epilogue: normalize & write concat layout ----
        const float inv0 = 1.f / l0r;
        const float inv1 = 1.f / l1r;
        const int qq = q0 + w * 16 + r0;
#pragma unroll
        for (int j = 0; j < 8; j++) {
            const int col = j * 8 + 2 * (lane & 3);
            float2 v0, v1;
            v0.x = o[j][0] * inv0; v0.y = o[j][1] * inv0;
            v1.x = o[j][2] * inv1; v1.y = o[j][3] * inv1;
            *(float2*)&Og[((size_t)(b * SEQ + qq))     * D_MODEL + h * DEPTH + col] = v0;
            *(float2*)&Og[((size_t)(b * SEQ + qq + 8)) * D_MODEL + h * DEPTH + col] = v1;
        }
    }
}

// ---------------------------------------------------------------------------
// Launch
// ---------------------------------------------------------------------------
extern "C" void kernel_launch(void* const* d_in, const int* in_sizes, int n_in,
                              void* d_out, int out_size)
{
    const float* v       = (const float*)d_in[0];
    const float* k       = (const float*)d_in[1];
    const float* q       = (const float*)d_in[2];
    // d_in[3] = mask (causal triu) -- analytic in attn kernel
    const float* wq_w    = (const float*)d_in[4];
    const float* wq_b    = (const float*)d_in[5];
    const float* wk_w    = (const float*)d_in[6];
    const float* wk_b    = (const float*)d_in[7];
    const float* wv_w    = (const float*)d_in[8];
    const float* wv_b    = (const float*)d_in[9];
    const float* dense_w = (const float*)d_in[10];
    const float* dense_b = (const float*)d_in[11];
    float* out = (float*)d_out;

    float *qh, *kh, *vh, *att;
    cudaGetSymbolAddress((void**)&qh,  g_qh);
    cudaGetSymbolAddress((void**)&kh,  g_kh);
    cudaGetSymbolAddress((void**)&vh,  g_vh);
    cudaGetSymbolAddress((void**)&att, g_att);

    cudaFuncSetAttribute(attn_tf32,
                         cudaFuncAttributeMaxDynamicSharedMemorySize,
                         ATTN_SMEM_BYTES);

    const dim3 pgrid(D_MODEL / 128, M_ROWS / 128, 3);   // (8, 32, 3)
    gemm_qkv<<<pgrid, 256>>>(q, k, v, wq_w, wq_b, wk_w, wk_b, wv_w, wv_b,
                             qh, kh, vh);

    const dim3 agrid(SEQ / 256, NUM_HEADS, BATCH);      // (8, 16, 2) paired tiles
    attn_tf32<<<agrid, ATTN_THREADS, ATTN_SMEM_BYTES>>>(qh, kh, vh, att);

    const dim3 dgrid(D_MODEL / 128, M_ROWS / 128);      // (8, 32)
    gemm_dense<<<dgrid, 256>>>(att, dense_w, dense_b, out);
}

// round 7
// speedup vs baseline: 4.3049x; 1.1125x over previous
#include <cuda_runtime.h>
#include <cstddef>
#include <cstdint>

#define D_MODEL   1024
#define NUM_HEADS 16
#define DEPTH     64
#define BATCH     2
#define SEQ       2048
#define M_ROWS    (BATCH * SEQ)   // 4096

// ---------------------------------------------------------------------------
// Scratch
// ---------------------------------------------------------------------------
__device__ float g_qh[BATCH * NUM_HEADS * SEQ * DEPTH];   // [B,H,S,64]
__device__ float g_kh[BATCH * NUM_HEADS * SEQ * DEPTH];
__device__ float g_vh[BATCH * NUM_HEADS * SEQ * DEPTH];
__device__ float g_att[BATCH * SEQ * D_MODEL];            // [B,S,H*64]

// ---------------------------------------------------------------------------
// Helpers
// ---------------------------------------------------------------------------
__device__ __forceinline__ unsigned f2tf(float f) {
    unsigned u;
    asm("cvt.rna.tf32.f32 %0, %1;" : "=r"(u) : "f"(f));
    return u;
}

__device__ __forceinline__ uint32_t smem_u32(const void* p) {
    uint32_t a;
    asm("{ .reg .u64 t; cvta.to.shared.u64 t, %1; cvt.u32.u64 %0, t; }" : "=r"(a) : "l"(p));
    return a;
}

__device__ __forceinline__ void mma8(float* c, const unsigned* a, const unsigned* b) {
    asm volatile(
        "mma.sync.aligned.m16n8k8.row.col.f32.tf32.tf32.f32 "
        "{%0,%1,%2,%3},{%4,%5,%6,%7},{%8,%9},{%0,%1,%2,%3};"
        : "+f"(c[0]), "+f"(c[1]), "+f"(c[2]), "+f"(c[3])
        : "r"(a[0]), "r"(a[1]), "r"(a[2]), "r"(a[3]), "r"(b[0]), "r"(b[1]));
}

__device__ __forceinline__ void ldm_x4(unsigned* d, uint32_t addr) {
    asm volatile("ldmatrix.sync.aligned.m8n8.x4.shared.b16 {%0,%1,%2,%3}, [%4];"
                 : "=r"(d[0]), "=r"(d[1]), "=r"(d[2]), "=r"(d[3]) : "r"(addr));
}

// ---------------------------------------------------------------------------
// tf32 GEMM via mma.sync + ldmatrix, double-buffered smem.
// C = A(M,K) @ W^T(N,K) + bias. Block 128x128, BK=16, 256 thr, 8 warps,
// warp tile 64x32. Smem rows = 64B (16 floats of K), swizzle c ^= (r>>1)&3.
// ---------------------------------------------------------------------------
#define BK 16

__device__ __forceinline__ void gemm_mma_core(
    const float* __restrict__ A, const float* __restrict__ W,
    const float* __restrict__ bias, float* __restrict__ C,
    int head_split, int m0, int n0)
{
    __shared__ __align__(16) unsigned As[2][128 * BK];
    __shared__ __align__(16) unsigned Bs[2][128 * BK];

    const int tid  = threadIdx.x;
    const int lane = tid & 31;
    const int w    = tid >> 5;
    const int wm   = w >> 2;            // 0..1
    const int wn   = w & 3;             // 0..3

    const uint32_t asb = smem_u32(&As[0][0]);
    const uint32_t bsb = smem_u32(&Bs[0][0]);

    float acc[4][4][4];
#pragma unroll
    for (int i = 0; i < 4; i++)
#pragma unroll
        for (int j = 0; j < 4; j++)
#pragma unroll
            for (int e = 0; e < 4; e++) acc[i][j][e] = 0.f;

    // staging geometry: thread t -> row t/2, float-cols (t&1)*8 .. +7
    const int srow = tid >> 1;
    const int scol = (tid & 1) * 8;
    const float* Ap = A + (size_t)(m0 + srow) * D_MODEL + scol;
    const float* Wp = W + (size_t)(n0 + srow) * D_MODEL + scol;

    // swizzled STS offsets (unsigned units): row*16 + (c ^ ((r>>1)&3))*4
    const int swb = (srow >> 1) & 3;
    const int c0s = ((scol >> 2) ^ swb) * 4;
    const int c1s = (((scol >> 2) + 1) ^ swb) * 4;
    unsigned* dA0 = &As[0][srow * 16 + c0s];
    unsigned* dA1 = &As[0][srow * 16 + c1s];
    unsigned* dB0 = &Bs[0][srow * 16 + c0s];
    unsigned* dB1 = &Bs[0][srow * 16 + c1s];

    float4 pa0 = *(const float4*)(Ap);
    float4 pa1 = *(const float4*)(Ap + 4);
    float4 pb0 = *(const float4*)(Wp);
    float4 pb1 = *(const float4*)(Wp + 4);

    // precompute ldmatrix lane addresses (byte offsets within one buffer)
    // A, m-tile i, kt: row = wm*64 + i*16 + (lane&7) + ((lane>>3)&1)*8
    //                  chunk = 2*kt + (lane>>4)
    uint32_t a_off[4][2], b_off[2][2];
#pragma unroll
    for (int i = 0; i < 4; i++) {
        const int r = wm * 64 + i * 16 + (lane & 7) + ((lane >> 3) & 1) * 8;
#pragma unroll
        for (int kt = 0; kt < 2; kt++) {
            const int c = 2 * kt + (lane >> 4);
            a_off[i][kt] = r * 64 + ((c ^ ((r >> 1) & 3)) << 4);
        }
    }
    // B, n-pair jp, kt: row = wn*32 + (2*jp + (lane>>4))*8 + (lane&7)
    //                   chunk = 2*kt + ((lane>>3)&1)
#pragma unroll
    for (int jp = 0; jp < 2; jp++) {
        const int r = wn * 32 + (2 * jp + (lane >> 4)) * 8 + (lane & 7);
#pragma unroll
        for (int kt = 0; kt < 2; kt++) {
            const int c = 2 * kt + ((lane >> 3) & 1);
            b_off[jp][kt] = r * 64 + ((c ^ ((r >> 1) & 3)) << 4);
        }
    }

    const int NSTEPS = D_MODEL / BK;   // 64
#pragma unroll 1
    for (int s = 0; s < NSTEPS; s++) {
        const int buf = s & 1;
        const int bofU = buf * 128 * BK;      // unsigned units
        // ---- stage prefetched regs -> smem[buf] ----
        uint4 u;
        u.x = f2tf(pa0.x); u.y = f2tf(pa0.y); u.z = f2tf(pa0.z); u.w = f2tf(pa0.w);
        *(uint4*)(dA0 + bofU) = u;
        u.x = f2tf(pa1.x); u.y = f2tf(pa1.y); u.z = f2tf(pa1.z); u.w = f2tf(pa1.w);
        *(uint4*)(dA1 + bofU) = u;
        u.x = f2tf(pb0.x); u.y = f2tf(pb0.y); u.z = f2tf(pb0.z); u.w = f2tf(pb0.w);
        *(uint4*)(dB0 + bofU) = u;
        u.x = f2tf(pb1.x); u.y = f2tf(pb1.y); u.z = f2tf(pb1.z); u.w = f2tf(pb1.w);
        *(uint4*)(dB1 + bofU) = u;
        __syncthreads();

        // ---- prefetch next K-slab ----
        if (s + 1 < NSTEPS) {
            const int k0 = (s + 1) * BK;
            pa0 = *(const float4*)(Ap + k0);
            pa1 = *(const float4*)(Ap + k0 + 4);
            pb0 = *(const float4*)(Wp + k0);
            pb1 = *(const float4*)(Wp + k0 + 4);
        }

        // ---- compute on smem[buf] ----
        const uint32_t abase = asb + buf * (128 * BK * 4);
        const uint32_t bbase = bsb + buf * (128 * BK * 4);
#pragma unroll
        for (int kt = 0; kt < 2; kt++) {
            unsigned bf[4][2];
            {
                unsigned t4[4];
                ldm_x4(t4, bbase + b_off[0][kt]);
                bf[0][0] = t4[0]; bf[0][1] = t4[1];
                bf[1][0] = t4[2]; bf[1][1] = t4[3];
                ldm_x4(t4, bbase + b_off[1][kt]);
                bf[2][0] = t4[0]; bf[2][1] = t4[1];
                bf[3][0] = t4[2]; bf[3][1] = t4[3];
            }
#pragma unroll
            for (int i = 0; i < 4; i++) {
                unsigned af[4];
                ldm_x4(af, abase + a_off[i][kt]);
#pragma unroll
                for (int j = 0; j < 4; j++) mma8(acc[i][j], af, bf[j]);
            }
        }
        // no trailing sync: next iter writes the OTHER buffer; this buffer is
        // only rewritten after the next sync, which all warps reach only after
        // finishing this compute.
    }

    // ---- epilogue ----
#pragma unroll
    for (int i = 0; i < 4; i++) {
#pragma unroll
        for (int j = 0; j < 4; j++) {
            const int m = m0 + wm * 64 + i * 16 + (lane >> 2);
            const int n = n0 + wn * 32 + j * 8 + 2 * (lane & 3);
            const float2 bb = *(const float2*)(bias + n);
            float2 v0, v1;
            v0.x = acc[i][j][0] + bb.x; v0.y = acc[i][j][1] + bb.y;
            v1.x = acc[i][j][2] + bb.x; v1.y = acc[i][j][3] + bb.y;
            if (head_split) {
                const int h = n >> 6, d = n & 63;
                const int b0r = m >> 11, s0r = m & (SEQ - 1);
                const int b1r = (m + 8) >> 11, s1r = (m + 8) & (SEQ - 1);
                *(float2*)&C[(((size_t)b0r * NUM_HEADS + h) * SEQ + s0r) * DEPTH + d] = v0;
                *(float2*)&C[(((size_t)b1r * NUM_HEADS + h) * SEQ + s1r) * DEPTH + d] = v1;
            } else {
                *(float2*)&C[(size_t)m * D_MODEL + n] = v0;
                *(float2*)&C[(size_t)(m + 8) * D_MODEL + n] = v1;
            }
        }
    }
}

__global__ __launch_bounds__(256, 2) void gemm_qkv(
    const float* __restrict__ q, const float* __restrict__ k, const float* __restrict__ v,
    const float* __restrict__ wq, const float* __restrict__ bq,
    const float* __restrict__ wk, const float* __restrict__ bk,
    const float* __restrict__ wv, const float* __restrict__ bv,
    float* __restrict__ qh, float* __restrict__ kh, float* __restrict__ vh)
{
    const int z = blockIdx.z;
    const float* A = (z == 0) ? q : (z == 1) ? k : v;
    const float* W = (z == 0) ? wq : (z == 1) ? wk : wv;
    const float* B = (z == 0) ? bq : (z == 1) ? bk : bv;
    float*       C = (z == 0) ? qh : (z == 1) ? kh : vh;
    gemm_mma_core(A, W, B, C, 1, blockIdx.y * 128, blockIdx.x * 128);
}

__global__ __launch_bounds__(256, 2) void gemm_dense(
    const float* __restrict__ A, const float* __restrict__ W,
    const float* __restrict__ bias, float* __restrict__ C)
{
    gemm_mma_core(A, W, bias, C, 0, blockIdx.y * 128, blockIdx.x * 128);
}

// ---------------------------------------------------------------------------
// FA2-style causal attention, tf32 mma (identical to the R3 passing version).
// ---------------------------------------------------------------------------
#define ATTN_THREADS 256
#define ATTN_SMEM_BYTES 65536

__global__ __launch_bounds__(ATTN_THREADS, 2) void attn_tf32(
    const float* __restrict__ Qg, const float* __restrict__ Kg,
    const float* __restrict__ Vg, float* __restrict__ Og)
{
    extern __shared__ unsigned ash[];

    const int tid  = threadIdx.x;
    const int lane = tid & 31;
    const int w    = tid >> 5;
    const int b    = blockIdx.z;
    const int h    = blockIdx.y;

    const size_t hoff = ((size_t)(b * NUM_HEADS + h) * SEQ) * DEPTH;
    const float* kb = Kg + hoff;
    const float* vb = Vg + hoff;

    const int r0 = lane >> 2;
    const int c0 = lane & 3;

#pragma unroll 1
    for (int pass = 0; pass < 2; pass++) {
        const int p  = pass ? (15 - (int)blockIdx.x) : (int)blockIdx.x;
        const int q0 = p * 128;

        unsigned qa[8][4];
        {
            const float* qbase = Qg + hoff + (size_t)(q0 + w * 16) * DEPTH;
#pragma unroll
            for (int kt = 0; kt < 8; kt++) {
                qa[kt][0] = f2tf(qbase[(size_t)(r0)     * DEPTH + kt * 8 + c0]);
                qa[kt][1] = f2tf(qbase[(size_t)(r0 + 8) * DEPTH + kt * 8 + c0]);
                qa[kt][2] = f2tf(qbase[(size_t)(r0)     * DEPTH + kt * 8 + c0 + 4]);
                qa[kt][3] = f2tf(qbase[(size_t)(r0 + 8) * DEPTH + kt * 8 + c0 + 4]);
            }
        }

        float o[8][4];
#pragma unroll
        for (int j = 0; j < 8; j++)
#pragma unroll
            for (int e = 0; e < 4; e++) o[j][e] = 0.f;
        float m0r = -1e30f, m1r = -1e30f;
        float l0r = 0.f,    l1r = 0.f;

        const int ntile = 2 * p + 2;
        const int qhiW  = q0 + w * 16 + 15;

        for (int t = 0; t < ntile; t++) {
            __syncthreads();
            for (int c = tid; c < 512; c += ATTN_THREADS) {
                const int key = c >> 3;
                const int kt  = c & 7;
                const float* src = kb + (size_t)(t * 64 + key) * DEPTH + kt * 8;
                const float4 a0 = *(const float4*)(src);
                const float4 a1 = *(const float4*)(src + 4);
                unsigned* dst = ash + ((kt * 8 + (key >> 3)) * 32 + (key & 7) * 4) * 2;
                uint4 s0, s1;
                s0.x = f2tf(a0.x); s0.y = f2tf(a1.x); s0.z = f2tf(a0.y); s0.w = f2tf(a1.y);
                s1.x = f2tf(a0.z); s1.y = f2tf(a1.z); s1.z = f2tf(a0.w); s1.w = f2tf(a1.w);
                ((uint4*)dst)[0] = s0;
                ((uint4*)dst)[1] = s1;
            }
            for (int u = tid; u < 512; u += ATTN_THREADS) {
                const int kg = u >> 6;
                const int kl = (u >> 4) & 3;
                const int dc = u & 15;
                const int keyA = kg * 8 + kl;
                const float4 va = *(const float4*)(vb + (size_t)(t * 64 + keyA)     * DEPTH + dc * 4);
                const float4 vB = *(const float4*)(vb + (size_t)(t * 64 + keyA + 4) * DEPTH + dc * 4);
                unsigned* dst = ash + 4096 + ((kg * 8 + (dc >> 1)) * 32 + (dc & 1) * 16 + kl) * 2;
                uint2 p0; p0.x = f2tf(va.x); p0.y = f2tf(vB.x); *(uint2*)(dst + 0)  = p0;
                uint2 p1; p1.x = f2tf(va.y); p1.y = f2tf(vB.y); *(uint2*)(dst + 8)  = p1;
                uint2 p2; p2.x = f2tf(va.z); p2.y = f2tf(vB.z); *(uint2*)(dst + 16) = p2;
                uint2 p3; p3.x = f2tf(va.w); p3.y = f2tf(vB.w); *(uint2*)(dst + 24) = p3;
            }
            __syncthreads();

            if (t * 64 > qhiW) continue;

            float s[8][4];
#pragma unroll
            for (int j = 0; j < 8; j++) {
#pragma unroll
                for (int e = 0; e < 4; e++) s[j][e] = 0.f;
#pragma unroll
                for (int kt = 0; kt < 8; kt++) {
                    const uint2 b2 = ((const uint2*)(ash + (kt * 8 + j) * 64))[lane];
                    unsigned bf[2] = {b2.x, b2.y};
                    mma8(s[j], qa[kt], bf);
                }
            }

            const bool diag = (t >= ntile - 2);
            const int qrow = q0 + w * 16 + r0;
            float mx0 = -1e30f, mx1 = -1e30f;
#pragma unroll
            for (int j = 0; j < 8; j++) {
#pragma unroll
                for (int e = 0; e < 4; e++) {
                    float vv = s[j][e] * 0.125f;
                    if (diag) {
                        const int key = t * 64 + j * 8 + 2 * (lane & 3) + (e & 1);
                        const int qq  = qrow + ((e >> 1) << 3);
                        if (key > qq) vv = -1e30f;
                    }
                    s[j][e] = vv;
                }
                mx0 = fmaxf(mx0, fmaxf(s[j][0], s[j][1]));
                mx1 = fmaxf(mx1, fmaxf(s[j][2], s[j][3]));
            }
            mx0 = fmaxf(mx0, __shfl_xor_sync(0xffffffffu, mx0, 1));
            mx0 = fmaxf(mx0, __shfl_xor_sync(0xffffffffu, mx0, 2));
            mx1 = fmaxf(mx1, __shfl_xor_sync(0xffffffffu, mx1, 1));
            mx1 = fmaxf(mx1, __shfl_xor_sync(0xffffffffu, mx1, 2));

            const float mn0 = fmaxf(m0r, mx0);
            const float mn1 = fmaxf(m1r, mx1);
            const float al0 = __expf(m0r - mn0);
            const float al1 = __expf(m1r - mn1);

            float ls0 = 0.f, ls1 = 0.f;
#pragma unroll
            for (int j = 0; j < 8; j++) {
                s[j][0] = __expf(s[j][0] - mn0); ls0 += s[j][0];
                s[j][1] = __expf(s[j][1] - mn0); ls0 += s[j][1];
                s[j][2] = __expf(s[j][2] - mn1); ls1 += s[j][2];
                s[j][3] = __expf(s[j][3] - mn1); ls1 += s[j][3];
            }
            ls0 += __shfl_xor_sync(0xffffffffu, ls0, 1);
            ls0 += __shfl_xor_sync(0xffffffffu, ls0, 2);
            ls1 += __shfl_xor_sync(0xffffffffu, ls1, 1);
            ls1 += __shfl_xor_sync(0xffffffffu, ls1, 2);

            l0r = l0r * al0 + ls0;
            l1r = l1r * al1 + ls1;
            m0r = mn0; m1r = mn1;

#pragma unroll
            for (int j = 0; j < 8; j++) {
                o[j][0] *= al0; o[j][1] *= al0;
                o[j][2] *= al1; o[j][3] *= al1;
            }

            __syncwarp();
#pragma unroll
            for (int j = 0; j < 8; j++) {
#pragma unroll
                for (int e = 0; e < 4; e++) {
                    const int cc = 2 * (lane & 3) + (e & 1);
                    const int rr = r0 + ((e >> 1) << 3);
                    ash[8192 + ((w * 8 + j) * 32 + (rr & 7) * 4 + (cc & 3)) * 4
                        + ((rr >> 3) & 1) + ((cc >> 2) & 1) * 2] = f2tf(s[j][e]);
                }
            }
            __syncwarp();

#pragma unroll
            for (int kt = 0; kt < 8; kt++) {
                const uint4 a4 = ((const uint4*)(ash + 8192 + (w * 8 + kt) * 128))[lane];
                unsigned af[4] = {a4.x, a4.y, a4.z, a4.w};
#pragma unroll
                for (int j = 0; j < 8; j++) {
                    const uint2 b2 = ((const uint2*)(ash + 4096 + (kt * 8 + j) * 64))[lane];
                    unsigned bf[2] = {b2.x, b2.y};
                    mma8(o[j], af, bf);
                }
            }
        }

        const float inv0 = 1.f / l0r;
        const float inv1 = 1.f / l1r;
        const int qq = q0 + w * 16 + r0;
#pragma unroll
        for (int j = 0; j < 8; j++) {
            const int col = j * 8 + 2 * (lane & 3);
            float2 v0, v1;
            v0.x = o[j][0] * inv0; v0.y = o[j][1] * inv0;
            v1.x = o[j][2] * inv1; v1.y = o[j][3] * inv1;
            *(float2*)&Og[((size_t)(b * SEQ + qq))     * D_MODEL + h * DEPTH + col] = v0;
            *(float2*)&Og[((size_t)(b * SEQ + qq + 8)) * D_MODEL + h * DEPTH + col] = v1;
        }
    }
}

// ---------------------------------------------------------------------------
// Launch
// ---------------------------------------------------------------------------
extern "C" void kernel_launch(void* const* d_in, const int* in_sizes, int n_in,
                              void* d_out, int out_size)
{
    const float* v       = (const float*)d_in[0];
    const float* k       = (const float*)d_in[1];
    const float* q       = (const float*)d_in[2];
    // d_in[3] = mask (causal triu) -- analytic in attn kernel
    const float* wq_w    = (const float*)d_in[4];
    const float* wq_b    = (const float*)d_in[5];
    const float* wk_w    = (const float*)d_in[6];
    const float* wk_b    = (const float*)d_in[7];
    const float* wv_w    = (const float*)d_in[8];
    const float* wv_b    = (const float*)d_in[9];
    const float* dense_w = (const float*)d_in[10];
    const float* dense_b = (const float*)d_in[11];
    float* out = (float*)d_out;

    float *qh, *kh, *vh, *att;
    cudaGetSymbolAddress((void**)&qh,  g_qh);
    cudaGetSymbolAddress((void**)&kh,  g_kh);
    cudaGetSymbolAddress((void**)&vh,  g_vh);
    cudaGetSymbolAddress((void**)&att, g_att);

    cudaFuncSetAttribute(attn_tf32,
                         cudaFuncAttributeMaxDynamicSharedMemorySize, ATTN_SMEM_BYTES);

    const dim3 pgrid(D_MODEL / 128, M_ROWS / 128, 3);   // (8, 32, 3)
    gemm_qkv<<<pgrid, 256>>>(q, k, v, wq_w, wq_b, wk_w, wk_b, wv_w, wv_b,
                             qh, kh, vh);

    const dim3 agrid(SEQ / 256, NUM_HEADS, BATCH);      // (8, 16, 2) paired tiles
    attn_tf32<<<agrid, ATTN_THREADS, ATTN_SMEM_BYTES>>>(qh, kh, vh, att);

    const dim3 dgrid(D_MODEL / 128, M_ROWS / 128);      // (8, 32)
    gemm_dense<<<dgrid, 256>>>(att, dense_w, dense_b, out);
}